// round 13
// baseline (speedup 1.0000x reference)
#include <cuda_runtime.h>
#include <cuda.h>
#include <math.h>

// Lowpass EMA scan: out[b,t,u] = (1-s[u])*x[b,t,u] + s[u]*prev
// R13: TMA (cp.async.bulk.tensor.2d) input staging replaces per-thread
// cp.async. One UTMALDG per 32KB tile (vs 2048 LDGSTS), mbarrier
// completion, 6-stage ring with 4 tiles in flight. Geometry and consume
// loop identical to the best kernel (R8): 128 blocks x 128 threads,
// register carry, coalesced __stcs stores.

#define LP_B   16
#define LP_T   2048
#define LP_U   1024
#define TPB    128
#define TT     64
#define NIT    (LP_T / TT)        // 32
#define RING   6
#define AHEAD  4
#define STAGE_FLOATS (TT * TPB)               // 8192 floats
#define TILE_BYTES   (STAGE_FLOATS * 4)       // 32768
#define SMEM_TILES   (RING * TILE_BYTES)      // 196608
#define SMEM_TOTAL   (SMEM_TILES + RING * 8 + 16)

__device__ __forceinline__ void mbar_init(unsigned mbar, unsigned count) {
    asm volatile("mbarrier.init.shared.b64 [%0], %1;" :: "r"(mbar), "r"(count) : "memory");
}
__device__ __forceinline__ void mbar_expect_tx(unsigned mbar, unsigned bytes) {
    asm volatile("mbarrier.arrive.expect_tx.shared.b64 _, [%0], %1;"
                 :: "r"(mbar), "r"(bytes) : "memory");
}
__device__ __forceinline__ void mbar_wait(unsigned mbar, unsigned phase) {
    asm volatile(
        "{\n\t.reg .pred P;\n"
        "WAIT_%=:\n\t"
        "mbarrier.try_wait.parity.acquire.cta.shared::cta.b64 P, [%0], %1, 0x989680;\n\t"
        "@!P bra WAIT_%=;\n\t}"
        :: "r"(mbar), "r"(phase) : "memory");
}
__device__ __forceinline__ void tma_load_2d_f32(unsigned smem_dst, const CUtensorMap* tm,
                                                int cx, int cy, unsigned mbar) {
    asm volatile(
        "cp.async.bulk.tensor.2d.shared::cta.global.tile.mbarrier::complete_tx::bytes "
        "[%0], [%1, {%2, %3}], [%4];"
        :: "r"(smem_dst), "l"(tm), "r"(cx), "r"(cy), "r"(mbar) : "memory");
}

__global__ void __launch_bounds__(TPB, 1)
lowpass_tma_kernel(const __grid_constant__ CUtensorMap tmap,
                   const float* __restrict__ level_var,
                   const float* __restrict__ smoothing_var,
                   float* __restrict__ out)
{
    extern __shared__ __align__(128) unsigned char smem_raw[];
    float* xs = reinterpret_cast<float*>(smem_raw);
    const unsigned smem_tiles_u = (unsigned)__cvta_generic_to_shared(smem_raw);
    const unsigned mbar_base    = smem_tiles_u + SMEM_TILES;

    const int tid = threadIdx.x;
    const int b   = blockIdx.x >> 3;          // 0..15
    const int u0  = (blockIdx.x & 7) << 7;    // 0,128,...,896
    const int u   = u0 + tid;
    const int row0 = b * LP_T;                // global row of this batch

    const float sv = smoothing_var[u];
    const float s  = 1.0f / (1.0f + expf(-sv));
    const float c  = 1.0f - s;
    float level    = level_var[u];

    float* __restrict__ ob = out + (size_t)b * LP_T * LP_U;

    if (tid == 0) {
#pragma unroll
        for (int p = 0; p < RING; p++)
            mbar_init(mbar_base + p * 8, 1);
        asm volatile("prefetch.tensormap [%0];" :: "l"(&tmap));
    }
    __syncthreads();

    // Prologue: issue tiles 0..AHEAD-1
    if (tid == 0) {
#pragma unroll
        for (int p = 0; p < AHEAD; p++) {
            const unsigned mb = mbar_base + p * 8;
            mbar_expect_tx(mb, TILE_BYTES);
            tma_load_2d_f32(smem_tiles_u + p * TILE_BYTES, &tmap,
                            u0, row0 + p * TT, mb);
        }
    }

    for (int it = 0; it < NIT; it++) {
        // Issue tile it+AHEAD (slot held tile it-2: consumed, fenced at it-1)
        if (tid == 0) {
            const int ls = it + AHEAD;
            if (ls < NIT) {
                const int slot = ls % RING;
                const unsigned mb = mbar_base + slot * 8;
                mbar_expect_tx(mb, TILE_BYTES);
                tma_load_2d_f32(smem_tiles_u + slot * TILE_BYTES, &tmap,
                                u0, row0 + ls * TT, mb);
            }
        }

        // Wait for tile it (phase flips every RING tiles)
        const int slot = it % RING;
        mbar_wait(mbar_base + slot * 8, (unsigned)((it / RING) & 1));

        // Consume: serial register carry, coalesced streaming stores
        const float* tile = xs + slot * STAGE_FLOATS;
        float* op = ob + (size_t)(it * TT) * LP_U + u;
#pragma unroll
        for (int t = 0; t < TT; t++) {
            level = fmaf(s, level, c * tile[t * TPB + tid]);
            __stcs(op + (size_t)t * LP_U, level);
        }
        __syncthreads();   // all threads done with 'slot' before its reuse
    }
}

// Host-side tensormap construction (driver entry point via cudart; no -lcuda)
typedef CUresult (*EncodeTiledFn)(
    CUtensorMap*, CUtensorMapDataType, cuuint32_t, void*,
    const cuuint64_t*, const cuuint64_t*, const cuuint32_t*, const cuuint32_t*,
    CUtensorMapInterleave, CUtensorMapSwizzle, CUtensorMapL2promotion,
    CUtensorMapFloatOOBfill);

extern "C" void kernel_launch(void* const* d_in, const int* in_sizes, int n_in,
                              void* d_out, int out_size)
{
    const float* x         = (const float*)d_in[0];  // [B,T,U]
    const float* level_var = (const float*)d_in[1];  // [1,U]
    const float* smoothing = (const float*)d_in[2];  // [1,U]
    float* out             = (float*)d_out;          // [B,T,U]

    static EncodeTiledFn encode_fn = nullptr;
    static CUtensorMap tmap;
    static const void* cached_ptr = nullptr;
    static int smem_set = 0;

    if (!smem_set) {
        cudaFuncSetAttribute(lowpass_tma_kernel,
                             cudaFuncAttributeMaxDynamicSharedMemorySize,
                             SMEM_TOTAL);
        smem_set = 1;
    }

    if (cached_ptr != (const void*)x) {
        if (!encode_fn) {
            void* fp = nullptr;
            cudaGetDriverEntryPoint("cuTensorMapEncodeTiled", &fp,
                                    cudaEnableDefault);
            encode_fn = (EncodeTiledFn)fp;
        }
        // 2D tensor: dim0 = U floats (contiguous), dim1 = B*T rows
        cuuint64_t gdim[2]    = { (cuuint64_t)LP_U, (cuuint64_t)(LP_B * LP_T) };
        cuuint64_t gstride[1] = { (cuuint64_t)LP_U * sizeof(float) };   // 4096B
        cuuint32_t box[2]     = { (cuuint32_t)TPB, (cuuint32_t)TT };    // 128 x 64
        cuuint32_t estr[2]    = { 1, 1 };
        encode_fn(&tmap, CU_TENSOR_MAP_DATA_TYPE_FLOAT32, 2, (void*)x,
                  gdim, gstride, box, estr,
                  CU_TENSOR_MAP_INTERLEAVE_NONE, CU_TENSOR_MAP_SWIZZLE_NONE,
                  CU_TENSOR_MAP_L2_PROMOTION_L2_128B,
                  CU_TENSOR_MAP_FLOAT_OOB_FILL_NONE);
        cached_ptr = (const void*)x;
    }

    const int blocks = LP_B * (LP_U / TPB);          // 128
    lowpass_tma_kernel<<<blocks, TPB, SMEM_TOTAL>>>(tmap, level_var, smoothing, out);
}

// round 14
// speedup vs baseline: 1.0190x; 1.0190x over previous
#include <cuda_runtime.h>
#include <cuda_bf16.h>
#include <math.h>

// Lowpass EMA scan: out[b,t,u] = (1-s[u])*x[b,t,u] + s[u]*prev
// CHAMPION (R8 config): thread-per-chain register carry + cp.async-staged
// input tiles. 6-stage ring, 4-tile prologue, next-tile issue hoisted
// above the wait -> ~5 tiles (160KB/SM) of reads in flight.
// Converged at the mixed R/W HBM ceiling (~5.7 TB/s for this pattern):
// depth, quantum, SM coverage, carry-chain, and TMA staging all proven
// non-binding in R7-R13.
//
// Block = 128 threads = chains (b, u0..u0+127); grid = 128 blocks.
// Tile = 64 t-rows x 512B (32KB). Loads: 16B cp.async.cg, coalesced.

#define LP_B   16
#define LP_T   2048
#define LP_U   1024
#define TPB    128           // threads = chains per block
#define TT     64            // t per tile
#define NIT    (LP_T / TT)   // 32
#define RING   6
#define STAGE_FLOATS (TT * TPB)                 // 8192 floats = 32KB
#define SMEM_BYTES   (RING * STAGE_FLOATS * 4)  // 192KB

__device__ __forceinline__ void cp_async16(float* smem_dst, const float* gsrc) {
    unsigned sdst = (unsigned)__cvta_generic_to_shared(smem_dst);
    asm volatile("cp.async.cg.shared.global [%0], [%1], 16;\n"
                 :: "r"(sdst), "l"(gsrc));
}
__device__ __forceinline__ void cp_async_commit() {
    asm volatile("cp.async.commit_group;\n" ::: "memory");
}
template <int N>
__device__ __forceinline__ void cp_async_wait() {
    asm volatile("cp.async.wait_group %0;\n" :: "n"(N) : "memory");
}

__global__ void __launch_bounds__(TPB, 1)
lowpass_cpasync_kernel(const float* __restrict__ x,
                       const float* __restrict__ level_var,
                       const float* __restrict__ smoothing_var,
                       float* __restrict__ out)
{
    extern __shared__ float xs[];   // [RING][TT][TPB]

    const int tid = threadIdx.x;
    const int b   = blockIdx.x >> 3;          // 0..15
    const int u0  = (blockIdx.x & 7) << 7;    // 0,128,...,896
    const int u   = u0 + tid;

    const float sv = smoothing_var[u];
    const float s  = 1.0f / (1.0f + expf(-sv));
    const float c  = 1.0f - s;
    float level    = level_var[u];

    const float* __restrict__ xb = x   + (size_t)b * LP_T * LP_U;
    float*       __restrict__ ob = out + (size_t)b * LP_T * LP_U;

    // Load mapping: thread covers rows (tid>>5)+4k, 16B at float col (tid&31)*4
    const int lrow = tid >> 5;          // 0..3
    const int lcol = (tid & 31) << 2;   // 0,4,...,124

    // Prologue: tiles 0..3 in flight (4 groups)
#pragma unroll
    for (int p = 0; p < 4; p++) {
        float* st = xs + p * STAGE_FLOATS;
#pragma unroll
        for (int k = 0; k < 16; k++) {
            const int r = lrow + 4 * k;
            cp_async16(st + r * TPB + lcol,
                       xb + (size_t)(p * TT + r) * LP_U + u0 + lcol);
        }
        cp_async_commit();
    }

    for (int it = 0; it < NIT; it++) {
        // Issue tile it+4 FIRST (slot (it+4)%RING held tile it-2, whose
        // consumption by all warps is fenced by the barrier at it-1).
        const int ls = it + 4;
        if (ls < NIT) {
            float* st = xs + (ls % RING) * STAGE_FLOATS;
#pragma unroll
            for (int k = 0; k < 16; k++) {
                const int r = lrow + 4 * k;
                cp_async16(st + r * TPB + lcol,
                           xb + (size_t)(ls * TT + r) * LP_U + u0 + lcol);
            }
        }
        cp_async_commit();      // empty groups near the end keep counts uniform

        cp_async_wait<4>();     // <=4 of 5 pending -> tile 'it' has landed
        __syncthreads();        // all threads' slices visible; old slot free

        // Consume tile it: serial carry, coalesced streaming stores
        const float* tile = xs + (it % RING) * STAGE_FLOATS;
        float* op = ob + (size_t)(it * TT) * LP_U + u;
#pragma unroll
        for (int t = 0; t < TT; t++) {
            level = fmaf(s, level, c * tile[t * TPB + tid]);
            __stcs(op + (size_t)t * LP_U, level);
        }
    }
}

extern "C" void kernel_launch(void* const* d_in, const int* in_sizes, int n_in,
                              void* d_out, int out_size)
{
    const float* x         = (const float*)d_in[0];  // [B,T,U]
    const float* level_var = (const float*)d_in[1];  // [1,U]
    const float* smoothing = (const float*)d_in[2];  // [1,U]
    float* out             = (float*)d_out;          // [B,T,U]

    static int smem_set = 0;
    if (!smem_set) {
        cudaFuncSetAttribute(lowpass_cpasync_kernel,
                             cudaFuncAttributeMaxDynamicSharedMemorySize,
                             SMEM_BYTES);
        smem_set = 1;
    }

    const int blocks = LP_B * (LP_U / TPB);          // 128
    lowpass_cpasync_kernel<<<blocks, TPB, SMEM_BYTES>>>(x, level_var, smoothing, out);
}